// round 10
// baseline (speedup 1.0000x reference)
#include <cuda_runtime.h>
#include <cstdint>

// ---------------- problem dimensions (fixed by the dataset) ----------------
#define B_IMG   8
#define N_PRED  100
#define T_TGT   160
#define M_TGT   20
#define K_CLS   80
#define HW      25600
#define BN_ROWS 800

// ---------------- mma.sync tf32 GEMM tiling ----------------
#define KSPLIT  20
#define KCHUNK  1280             // HW / KSPLIT
#define BK      16
#define NIT     (KCHUNK / BK)    // 80
#define MTILE   128
#define NTILE   80               // per-CTA N (z splits 160 into 2)
#define MBLKS   7                // ceil(800/128)
#define LDA_S   20               // smem row stride in floats (16 + 4 pad)
#define A_FLOATS (MTILE * LDA_S)           // 2560
#define STAGE_F  (A_FLOATS + NTILE * LDA_S) // 4160
#define NSTAGE  6
#define SMEM_BYTES (NSTAGE * STAGE_F * 4)   // 99840 per CTA

// ---------------- scratch (no allocations allowed) ----------------
__device__ float g_partial[KSPLIT * BN_ROWS * T_TGT];   // 10.24 MB, [ks][row][col]
__device__ float g_pnp[KSPLIT * BN_ROWS];
__device__ float g_tnp[KSPLIT * T_TGT];

// ---------------- helpers ----------------
__device__ __forceinline__ uint32_t smem_u32(const void* p) {
    uint32_t a;
    asm("{ .reg .u64 t; cvta.to.shared.u64 t, %1; cvt.u32.u64 %0, t; }" : "=r"(a) : "l"(p));
    return a;
}
__device__ __forceinline__ void cp16(uint32_t dst, const void* src, int sz) {
    asm volatile("cp.async.cg.shared.global [%0], [%1], 16, %2;"
                 :: "r"(dst), "l"(src), "r"(sz) : "memory");
}
__device__ __forceinline__ void cp_commit() {
    asm volatile("cp.async.commit_group;" ::: "memory");
}
__device__ __forceinline__ void mma_tf32(float* c, const uint32_t* a, const uint32_t* b) {
    asm volatile(
        "mma.sync.aligned.m16n8k8.row.col.f32.tf32.tf32.f32 "
        "{%0,%1,%2,%3}, {%4,%5,%6,%7}, {%8,%9}, {%0,%1,%2,%3};"
        : "+f"(c[0]), "+f"(c[1]), "+f"(c[2]), "+f"(c[3])
        : "r"(a[0]), "r"(a[1]), "r"(a[2]), "r"(a[3]), "r"(b[0]), "r"(b[1]));
}
// ldmatrix x4 on b16: four 8x8 b16 tiles == four 8x4 tf32 tiles; per-thread
// distribution (row=lane>>2, col=lane&3) matches the tf32 m16n8k8 fragment.
__device__ __forceinline__ void ldsm4(uint32_t* r, uint32_t addr) {
    asm volatile("ldmatrix.sync.aligned.m8n8.x4.shared.b16 {%0,%1,%2,%3}, [%4];"
                 : "=r"(r[0]), "=r"(r[1]), "=r"(r[2]), "=r"(r[3]) : "r"(addr));
}

// ---------------- tf32 mma.sync split-K split-N GEMM + fused sumsq ----------------
// grid (7, 20, 2): bx = M-block, by = k-split, bz = N-half. 2 CTAs/SM.
// Each warp: 16 rows (warpM = wid) x 80 cols.
__global__ void __launch_bounds__(256, 2)
gemm_mma_kernel(const float* __restrict__ A, const float* __restrict__ Bm,
                float* __restrict__ P, float* __restrict__ pnp, float* __restrict__ tnp)
{
    extern __shared__ __align__(16) float dsm[];

    const int tid   = threadIdx.x;
    const int wid   = tid >> 5;
    const int lane  = tid & 31;
    const int gid   = lane >> 2;     // 0..7
    const int tig   = lane & 3;      // 0..3
    const int bx    = blockIdx.x;
    const int by    = blockIdx.y;
    const int bz    = blockIdx.z;
    const int mBase = bx * MTILE;
    const int kBase = by * KCHUNK;
    const int nBase = bz * NTILE;

    float acc[10][4];
#pragma unroll
    for (int tn = 0; tn < 10; tn++)
#pragma unroll
        for (int i = 0; i < 4; i++) acc[tn][i] = 0.f;

    const uint32_t sbase = smem_u32(dsm);

    // ldmatrix per-thread address offsets (bytes, within a stage)
    const int q = lane >> 3;
    const uint32_t offA = ((wid * 16 + (q & 1) * 8 + (lane & 7)) * LDA_S
                           + (q >> 1) * 4) * 4;
    const uint32_t offB = (A_FLOATS
                           + ((q >> 1) * 8 + (lane & 7)) * LDA_S
                           + (q & 1) * 4) * 4;

    const float* Bz = Bm + (size_t)nBase * HW;

    auto issue = [&](int t) {
        const int buf = t % NSTAGE;
        const uint32_t sb = sbase + buf * (STAGE_F * 4);
        const int kOff = kBase + t * BK;
        // A: 128 rows x 4 cp16 = 512 -> 2 per thread
#pragma unroll
        for (int i = 0; i < 2; ++i) {
            const int f = tid * 2 + i;
            const int row = f >> 2, kq = f & 3;
            const int grow = mBase + row;
            const int ok = grow < BN_ROWS;
            const float* src = A + (size_t)(ok ? grow : 0) * HW + kOff + kq * 4;
            cp16(sb + row * (LDA_S * 4) + kq * 16, src, ok ? 16 : 0);
        }
        // B: 80 rows x 4 cp16 = 320 -> tid, tid+256 (if < 320)
#pragma unroll
        for (int i = 0; i < 2; ++i) {
            const int f = tid + i * 256;
            if (f < NTILE * 4) {
                const int row = f >> 2, kq = f & 3;
                cp16(sb + (A_FLOATS * 4) + row * (LDA_S * 4) + kq * 16,
                     Bz + (size_t)row * HW + kOff + kq * 4, 16);
            }
        }
        cp_commit();
    };

    // fused sumsq bookkeeping
    const int sq_arow = tid >> 1;              // 0..127
    const int sq_akh  = (tid & 1) * 8;         // 0 or 8
    const int sq_m    = tid >> 4;              // 0..15 (use rows bx+7m < 80)
    const int sq_k    = tid & 15;
    const int sq_br   = bx + 7 * sq_m;
    const bool sq_bok = (sq_br < NTILE);
    float accA = 0.f, accB = 0.f;

    auto compute = [&](int t) {
        const int buf = t % NSTAGE;
        const uint32_t sb = sbase + buf * (STAGE_F * 4);
        const float* asf = dsm + buf * STAGE_F;
        const float* bsf = asf + A_FLOATS;

        // fused sumsq from smem
        {
            const float2* a2 = (const float2*)(asf + sq_arow * LDA_S + sq_akh);
#pragma unroll
            for (int i = 0; i < 4; ++i) {
                float2 v = a2[i];
                accA += v.x * v.x + v.y * v.y;
            }
            if (sq_bok) {
                float b0 = bsf[sq_br * LDA_S + sq_k];
                accB += b0 * b0;
            }
        }

#pragma unroll
        for (int s = 0; s < 2; ++s) {
            uint32_t af[4], bf[5][4];
            ldsm4(af, sb + offA + s * 32);
#pragma unroll
            for (int tp = 0; tp < 5; tp++)
                ldsm4(bf[tp], sb + offB + tp * (16 * LDA_S * 4) + s * 32);
#pragma unroll
            for (int tp = 0; tp < 5; tp++) {
                mma_tf32(acc[2 * tp],     af, &bf[tp][0]);
                mma_tf32(acc[2 * tp + 1], af, &bf[tp][2]);
            }
        }
    };

    // prologue: 4 stages in flight
    issue(0); issue(1); issue(2); issue(3);

    for (int t = 0; t < NIT; t += 2) {
        if (t + 4 < NIT) { issue(t + 4); issue(t + 5); }
        if (t <= NIT - 6)      asm volatile("cp.async.wait_group 4;" ::: "memory");
        else if (t == NIT - 4) asm volatile("cp.async.wait_group 2;" ::: "memory");
        else                   asm volatile("cp.async.wait_group 0;" ::: "memory");
        __syncthreads();

        compute(t);
        compute(t + 1);
        __syncthreads();   // stages t,t+1 consumed before re-fill next iteration
    }

    // ---- sumsq reduction (smem reuse after mainloop) ----
    dsm[tid] = accA;
    dsm[256 + tid] = sq_bok ? accB : 0.f;
    __syncthreads();
    if (tid < 128) {
        if (bz == 0) {                        // A norms once
            const float s = dsm[2 * tid] + dsm[2 * tid + 1];
            const int gr = mBase + tid;
            if (gr < BN_ROWS) pnp[by * BN_ROWS + gr] = s;
        }
    } else if (tid < 140) {                   // 12 B-row groups (bx + 7m < 80)
        const int m = tid - 128;
        const int r = bx + 7 * m;
        if (r < NTILE) {
            const int base = 256 + m * 16;
            float s = 0.f;
#pragma unroll
            for (int k = 0; k < 16; ++k) s += dsm[base + k];
            tnp[by * T_TGT + nBase + r] = s;
        }
    }

    // ---- epilogue: write P[ks][row][col] ----
    float* dst = P + (size_t)by * (BN_ROWS * T_TGT);
    const int r0 = mBase + wid * 16 + gid;
    const int r1 = r0 + 8;
#pragma unroll
    for (int tn = 0; tn < 10; tn++) {
        const int col = nBase + tn * 8 + tig * 2;
        if (r0 < BN_ROWS)
            *(float2*)&dst[(size_t)r0 * T_TGT + col] = make_float2(acc[tn][0], acc[tn][1]);
        if (r1 < BN_ROWS)
            *(float2*)&dst[(size_t)r1 * T_TGT + col] = make_float2(acc[tn][2], acc[tn][3]);
    }
}

// ---------------- finalize: ksplit-sum + norms + dice + focal -> C ----------------
__global__ void __launch_bounds__(256) finalize_kernel(const float* __restrict__ P,
                                                       const float* __restrict__ pnp,
                                                       const float* __restrict__ tnp,
                                                       const float* __restrict__ logits,
                                                       const int*   __restrict__ ids,
                                                       float* __restrict__ C)
{
    const int base = (blockIdx.x * 256 + threadIdx.x) * 4;
    if (base >= BN_ROWS * T_TGT) return;
    const int bn = base / T_TGT;
    const int t0 = base - bn * T_TGT;

    float4 dot = make_float4(0.f, 0.f, 0.f, 0.f);
    float4 tn4 = make_float4(0.f, 0.f, 0.f, 0.f);
    float  pnv = 0.f;
#pragma unroll
    for (int ks = 0; ks < KSPLIT; ks++) {
        float4 p4 = *(const float4*)&P[(size_t)ks * (BN_ROWS * T_TGT) + base];
        dot.x += p4.x; dot.y += p4.y; dot.z += p4.z; dot.w += p4.w;
        float4 t4 = *(const float4*)&tnp[ks * T_TGT + t0];
        tn4.x += t4.x; tn4.y += t4.y; tn4.z += t4.z; tn4.w += t4.w;
        pnv += pnp[ks * BN_ROWS + bn];
    }

    float res[4];
    const float d4[4] = {dot.x, dot.y, dot.z, dot.w};
    const float tt[4] = {tn4.x, tn4.y, tn4.z, tn4.w};
#pragma unroll
    for (int q = 0; q < 4; ++q) {
        const float den = pnv + tt[q];
        const float score = -((2.0f * d4[q] + 1e-4f) / (den + 1e-4f));
        const int id = ids[t0 + q];
        const float x = logits[bn * K_CLS + id];
        float pl;
        if (x >= 0.f) pl = 1.f / (1.f + expf(-x));
        else { float e = expf(x); pl = e / (1.f + e); }
        const float pos = 0.25f * (1.f - pl) * (1.f - pl) * (-logf(pl + 1e-8f));
        const float neg = 0.75f * pl * pl * (-logf(1.f - pl + 1e-8f));
        res[q] = score * 2.0f + (pos - neg);
    }
    *(float4*)&C[base] = make_float4(res[0], res[1], res[2], res[3]);
}

// ---------------- Jonker-Volgenant LSA, register-resident, one warp/image ----------------
__device__ __forceinline__ unsigned long long dkey(double d) {
    long long b = __double_as_longlong(d);
    return (unsigned long long)(b >= 0 ? (b ^ 0x8000000000000000LL) : ~b);
}
__device__ __forceinline__ double inv_dkey(unsigned long long k) {
    long long b = (k & 0x8000000000000000ULL) ? (long long)(k ^ 0x8000000000000000ULL)
                                              : ~(long long)k;
    return __longlong_as_double(b);
}

__global__ void __launch_bounds__(32) lsa_kernel(const float* __restrict__ C,
                                                 float* __restrict__ out_rows,
                                                 float* __restrict__ out_cols)
{
    const int b    = blockIdx.x;
    const int lane = threadIdx.x;
    const double INFD = 1e18;

    __shared__ double c[M_TGT][N_PRED];
    __shared__ double u[M_TGT + 1];
    __shared__ int    p[N_PRED + 1];
    __shared__ int    way[N_PRED + 1];

    for (int idx = lane; idx < M_TGT * N_PRED; idx += 32) {
        int t = idx / N_PRED, n = idx - t * N_PRED;
        c[t][n] = (double)C[(size_t)b * (N_PRED * T_TGT) + (size_t)n * T_TGT + b * M_TGT + t];
    }
    for (int j = lane; j <= N_PRED; j += 32) { p[j] = 0; way[j] = 0; }
    if (lane <= M_TGT) u[lane] = 0.0;

    const int jq0 = 1 + lane, jq1 = 33 + lane, jq2 = 65 + lane, jq3 = 97 + lane;
    const bool v3 = (jq3 <= N_PRED);
    double v_r0 = 0, v_r1 = 0, v_r2 = 0, v_r3 = 0;
    double m_r0, m_r1, m_r2, m_r3;
    bool  u_r0, u_r1, u_r2, u_r3;
    __syncwarp();

    for (int i = 1; i <= M_TGT; ++i) {
        if (lane == 0) p[0] = i;
        m_r0 = m_r1 = m_r2 = m_r3 = INFD;
        u_r0 = u_r1 = u_r2 = u_r3 = false;
        __syncwarp();

        int j0 = 0;
        while (true) {
            u_r0 |= (jq0 == j0); u_r1 |= (jq1 == j0);
            u_r2 |= (jq2 == j0); u_r3 |= (jq3 == j0);

            const int i0 = p[j0];
            const double ui0 = u[i0];
            const double* crow = c[i0 - 1];

            unsigned long long bestKey = 0xFFFFFFFFFFFFFFFFULL;
            int bestJ = 0x7FFFFFFF;
            if (!u_r0) {
                double cur = (crow[jq0 - 1] - ui0) - v_r0;
                if (cur < m_r0) { m_r0 = cur; way[jq0] = j0; }
                unsigned long long k = dkey(m_r0);
                if (k < bestKey) { bestKey = k; bestJ = jq0; }
            }
            if (!u_r1) {
                double cur = (crow[jq1 - 1] - ui0) - v_r1;
                if (cur < m_r1) { m_r1 = cur; way[jq1] = j0; }
                unsigned long long k = dkey(m_r1);
                if (k < bestKey) { bestKey = k; bestJ = jq1; }
            }
            if (!u_r2) {
                double cur = (crow[jq2 - 1] - ui0) - v_r2;
                if (cur < m_r2) { m_r2 = cur; way[jq2] = j0; }
                unsigned long long k = dkey(m_r2);
                if (k < bestKey) { bestKey = k; bestJ = jq2; }
            }
            if (v3 && !u_r3) {
                double cur = (crow[jq3 - 1] - ui0) - v_r3;
                if (cur < m_r3) { m_r3 = cur; way[jq3] = j0; }
                unsigned long long k = dkey(m_r3);
                if (k < bestKey) { bestKey = k; bestJ = jq3; }
            }

            const unsigned hi = (unsigned)(bestKey >> 32);
            const unsigned minHi = __reduce_min_sync(0xffffffff, hi);
            const unsigned lo = (hi == minHi) ? (unsigned)bestKey : 0xffffffffu;
            const unsigned minLo = __reduce_min_sync(0xffffffff, lo);
            const unsigned jc = (hi == minHi && (unsigned)bestKey == minLo)
                                ? (unsigned)bestJ : 0x7fffffffu;
            const int j1 = (int)__reduce_min_sync(0xffffffff, jc);
            const double delta = inv_dkey(((unsigned long long)minHi << 32) | minLo);

            if (u_r0) { u[p[jq0]] += delta; v_r0 -= delta; } else { m_r0 -= delta; }
            if (u_r1) { u[p[jq1]] += delta; v_r1 -= delta; } else { m_r1 -= delta; }
            if (u_r2) { u[p[jq2]] += delta; v_r2 -= delta; } else { m_r2 -= delta; }
            if (v3) { if (u_r3) { u[p[jq3]] += delta; v_r3 -= delta; } else { m_r3 -= delta; } }
            if (lane == 0) u[p[0]] += delta;

            __syncwarp();
            j0 = j1;
            if (p[j0] == 0) break;
        }

        if (lane == 0) {
            int jj = j0;
            while (jj != 0) { int jn = way[jj]; p[jj] = p[jn]; jj = jn; }
        }
        __syncwarp();
    }

    if (lane == 0) {
        int k = 0;
        for (int j = 1; j <= N_PRED; j++) {
            if (p[j] != 0) {
                out_rows[b * M_TGT + k] = (float)(j - 1);
                out_cols[b * M_TGT + k] = (float)(p[j] - 1);
                k++;
            }
        }
    }
}

// ---------------- launch ----------------
extern "C" void kernel_launch(void* const* d_in, const int* in_sizes, int n_in,
                              void* d_out, int out_size)
{
    const float* pred_masks   = (const float*)d_in[0];   // (8,100,160,160)
    const float* pred_logits  = (const float*)d_in[1];   // (8,100,80)
    const float* target_masks = (const float*)d_in[2];   // (160,160,160)
    const int*   tgt_ids      = (const int*)d_in[3];     // (160,)
    float* out = (float*)d_out;                          // [C | rows | cols]

    float* d_partial; cudaGetSymbolAddress((void**)&d_partial, g_partial);
    float* d_pnp;     cudaGetSymbolAddress((void**)&d_pnp, g_pnp);
    float* d_tnp;     cudaGetSymbolAddress((void**)&d_tnp, g_tnp);

    cudaFuncSetAttribute(gemm_mma_kernel,
                         cudaFuncAttributeMaxDynamicSharedMemorySize, SMEM_BYTES);

    dim3 ggrid(MBLKS, KSPLIT, 2);
    gemm_mma_kernel<<<ggrid, 256, SMEM_BYTES>>>(pred_masks, target_masks,
                                                d_partial, d_pnp, d_tnp);

    finalize_kernel<<<(BN_ROWS * T_TGT / 4 + 255) / 256, 256>>>(d_partial, d_pnp, d_tnp,
                                                                pred_logits, tgt_ids, out);

    lsa_kernel<<<B_IMG, 32>>>(out,
                              out + BN_ROWS * T_TGT,
                              out + BN_ROWS * T_TGT + B_IMG * M_TGT);
}

// round 11
// speedup vs baseline: 1.2094x; 1.2094x over previous
#include <cuda_runtime.h>
#include <cstdint>

// ---------------- problem dimensions (fixed by the dataset) ----------------
#define B_IMG   8
#define N_PRED  100
#define T_TGT   160
#define M_TGT   20
#define K_CLS   80
#define HW      25600
#define BN_ROWS 800

// ---------------- mma.sync tf32 GEMM tiling ----------------
#define KSPLIT  20
#define KCHUNK  1280             // HW / KSPLIT
#define BK      16
#define NIT     (KCHUNK / BK)    // 80
#define MTILE   128
#define MBLKS   7                // ceil(800/128)
#define LDA_S   20               // smem row stride in floats (16 + 4 pad)
#define STAGE_F 5760             // floats per stage: 128*20 + 160*20
#define NSTAGE  8
#define SMEM_BYTES (NSTAGE * STAGE_F * 4)   // 184320

// ---------------- scratch (no allocations allowed) ----------------
__device__ float g_partial[KSPLIT * BN_ROWS * T_TGT];   // 10.24 MB, [ks][row][col]
__device__ float g_pnp[KSPLIT * BN_ROWS];
__device__ float g_tnp[KSPLIT * T_TGT];

// ---------------- helpers ----------------
__device__ __forceinline__ uint32_t smem_u32(const void* p) {
    uint32_t a;
    asm("{ .reg .u64 t; cvta.to.shared.u64 t, %1; cvt.u32.u64 %0, t; }" : "=r"(a) : "l"(p));
    return a;
}
__device__ __forceinline__ void cp16(uint32_t dst, const void* src, int sz) {
    asm volatile("cp.async.cg.shared.global [%0], [%1], 16, %2;"
                 :: "r"(dst), "l"(src), "r"(sz) : "memory");
}
__device__ __forceinline__ void cp_commit() {
    asm volatile("cp.async.commit_group;" ::: "memory");
}
__device__ __forceinline__ void mma_tf32(float* c, const uint32_t* a, const uint32_t* b) {
    asm volatile(
        "mma.sync.aligned.m16n8k8.row.col.f32.tf32.tf32.f32 "
        "{%0,%1,%2,%3}, {%4,%5,%6,%7}, {%8,%9}, {%0,%1,%2,%3};"
        : "+f"(c[0]), "+f"(c[1]), "+f"(c[2]), "+f"(c[3])
        : "r"(a[0]), "r"(a[1]), "r"(a[2]), "r"(a[3]), "r"(b[0]), "r"(b[1]));
}
// ldmatrix x4 on b16: four 8x8 b16 tiles == four 8x4 tf32 tiles; per-thread
// distribution (row=lane>>2, col=lane&3) matches the tf32 m16n8k8 fragment.
__device__ __forceinline__ void ldsm4(uint32_t* r, uint32_t addr) {
    asm volatile("ldmatrix.sync.aligned.m8n8.x4.shared.b16 {%0,%1,%2,%3}, [%4];"
                 : "=r"(r[0]), "=r"(r[1]), "=r"(r[2]), "=r"(r[3]) : "r"(addr));
}

// ---------------- tf32 mma.sync split-K GEMM + fused sumsq ----------------
// MTILE=128, 1 CTA/SM, grid (7,20)=140. 8-stage pipeline, 4 k-tiles / barrier,
// ldmatrix fragment loads.
__global__ void __launch_bounds__(256, 1)
gemm_mma_kernel(const float* __restrict__ A, const float* __restrict__ Bm,
                float* __restrict__ P, float* __restrict__ pnp, float* __restrict__ tnp)
{
    extern __shared__ __align__(16) float dsm[];

    const int tid   = threadIdx.x;
    const int wid   = tid >> 5;
    const int lane  = tid & 31;
    const int gid   = lane >> 2;     // 0..7
    const int tig   = lane & 3;      // 0..3
    const int warpM = wid >> 1;      // 0..3 -> 32 rows each
    const int warpN = wid & 1;       // 0..1 -> 80 cols each
    const int bx    = blockIdx.x;
    const int by    = blockIdx.y;
    const int mBase = bx * MTILE;
    const int kBase = by * KCHUNK;

    float acc[2][10][4];
#pragma unroll
    for (int tm = 0; tm < 2; tm++)
#pragma unroll
        for (int tn = 0; tn < 10; tn++)
#pragma unroll
            for (int i = 0; i < 4; i++) acc[tm][tn][i] = 0.f;

    const uint32_t sbase = smem_u32(dsm);

    // ldmatrix per-thread address offsets (bytes, within a stage)
    const int q = lane >> 3;
    const uint32_t offA = ((warpM * 32 + (q & 1) * 8 + (lane & 7)) * LDA_S
                           + (q >> 1) * 4) * 4;
    const uint32_t offB = (MTILE * LDA_S
                           + (warpN * 80 + (q >> 1) * 8 + (lane & 7)) * LDA_S
                           + (q & 1) * 4) * 4;

    auto issue = [&](int t) {
        const int buf = t & (NSTAGE - 1);
        const uint32_t sb = sbase + buf * (STAGE_F * 4);
        const int kOff = kBase + t * BK;
#pragma unroll
        for (int i = 0; i < 2; ++i) {
            const int f = tid * 2 + i;
            const int row = f >> 2, kq = f & 3;
            const int grow = mBase + row;
            const int ok = grow < BN_ROWS;
            const float* src = A + (size_t)(ok ? grow : 0) * HW + kOff + kq * 4;
            cp16(sb + row * (LDA_S * 4) + kq * 16, src, ok ? 16 : 0);
        }
#pragma unroll
        for (int i = 0; i < 3; ++i) {
            const int f = tid + i * 256;
            if (f < T_TGT * 4) {
                const int row = f >> 2, kq = f & 3;
                cp16(sb + (MTILE * LDA_S * 4) + row * (LDA_S * 4) + kq * 16,
                     Bm + (size_t)row * HW + kOff + kq * 4, 16);
            }
        }
        cp_commit();
    };

    // fused sumsq bookkeeping
    const int sq_arow = tid >> 1;              // 0..127
    const int sq_akh  = (tid & 1) * 8;         // 0 or 8
    const int sq_m    = tid >> 4;              // 0..15
    const int sq_k    = tid & 15;
    const int sq_br0  = bx + 7 * sq_m;               // < 160 always
    const int sq_br1  = bx + 7 * (sq_m + 16);        // may be >= 160
    const bool sq_b1ok = (sq_br1 < T_TGT);
    float accA = 0.f, accB0 = 0.f, accB1 = 0.f;

    auto compute = [&](int t) {
        const int buf = t & (NSTAGE - 1);
        const uint32_t sb = sbase + buf * (STAGE_F * 4);
        const float* asf = dsm + buf * STAGE_F;
        const float* bsf = asf + MTILE * LDA_S;

        // fused sumsq from smem
        {
            const float2* a2 = (const float2*)(asf + sq_arow * LDA_S + sq_akh);
#pragma unroll
            for (int i = 0; i < 4; ++i) {
                float2 v = a2[i];
                accA += v.x * v.x + v.y * v.y;
            }
            float b0 = bsf[sq_br0 * LDA_S + sq_k];
            accB0 += b0 * b0;
            if (sq_b1ok) {
                float b1 = bsf[sq_br1 * LDA_S + sq_k];
                accB1 += b1 * b1;
            }
        }

#pragma unroll
        for (int s = 0; s < 2; ++s) {
            uint32_t af[2][4], bf[5][4];
            ldsm4(af[0], sb + offA + s * 32);
            ldsm4(af[1], sb + offA + (16 * LDA_S * 4) + s * 32);
#pragma unroll
            for (int tp = 0; tp < 5; tp++)
                ldsm4(bf[tp], sb + offB + tp * (16 * LDA_S * 4) + s * 32);
#pragma unroll
            for (int tm = 0; tm < 2; tm++)
#pragma unroll
                for (int tp = 0; tp < 5; tp++) {
                    mma_tf32(acc[tm][2 * tp],     af[tm], &bf[tp][0]);
                    mma_tf32(acc[tm][2 * tp + 1], af[tm], &bf[tp][2]);
                }
        }
    };

    // prologue: 4 stages in flight (stages 0..3)
    issue(0); issue(1); issue(2); issue(3);

    for (int t = 0; t < NIT; t += 4) {
        // tiles t..t+3 are the only outstanding groups -> drain them all
        asm volatile("cp.async.wait_group 0;" ::: "memory");
        __syncthreads();
        // refill the 4 stages consumed LAST iteration (disjoint from t..t+3)
        if (t + 4 < NIT) { issue(t + 4); issue(t + 5); issue(t + 6); issue(t + 7); }

        compute(t);
        compute(t + 1);
        compute(t + 2);
        compute(t + 3);
    }
    __syncthreads();   // protect smem reuse below

    // ---- sumsq reduction (smem reuse after mainloop) ----
    dsm[tid] = accA;
    dsm[256 + tid] = accB0;
    dsm[512 + tid] = sq_b1ok ? accB1 : 0.f;
    __syncthreads();
    if (tid < 128) {
        const float s = dsm[2 * tid] + dsm[2 * tid + 1];
        const int gr = mBase + tid;
        if (gr < BN_ROWS) pnp[by * BN_ROWS + gr] = s;
    } else if (tid < 160) {
        const int m = tid - 128;
        const int r = bx + 7 * m;
        if (r < T_TGT) {
            const int base = (m < 16) ? (256 + m * 16) : (512 + (m - 16) * 16);
            float s = 0.f;
#pragma unroll
            for (int k = 0; k < 16; ++k) s += dsm[base + k];
            tnp[by * T_TGT + r] = s;
        }
    }

    // ---- epilogue: write P[ks][row][col] ----
    float* dst = P + (size_t)by * (BN_ROWS * T_TGT);
#pragma unroll
    for (int tm = 0; tm < 2; tm++) {
        const int r0 = mBase + warpM * 32 + tm * 16 + gid;
        const int r1 = r0 + 8;
#pragma unroll
        for (int tn = 0; tn < 10; tn++) {
            const int col = warpN * 80 + tn * 8 + tig * 2;
            if (r0 < BN_ROWS)
                *(float2*)&dst[(size_t)r0 * T_TGT + col] = make_float2(acc[tm][tn][0], acc[tm][tn][1]);
            if (r1 < BN_ROWS)
                *(float2*)&dst[(size_t)r1 * T_TGT + col] = make_float2(acc[tm][tn][2], acc[tm][tn][3]);
        }
    }
}

// ---------------- finalize: ksplit-sum + norms + dice + focal -> C ----------------
__global__ void __launch_bounds__(256) finalize_kernel(const float* __restrict__ P,
                                                       const float* __restrict__ pnp,
                                                       const float* __restrict__ tnp,
                                                       const float* __restrict__ logits,
                                                       const int*   __restrict__ ids,
                                                       float* __restrict__ C)
{
    const int base = (blockIdx.x * 256 + threadIdx.x) * 4;
    if (base >= BN_ROWS * T_TGT) return;
    const int bn = base / T_TGT;
    const int t0 = base - bn * T_TGT;

    float4 dot = make_float4(0.f, 0.f, 0.f, 0.f);
    float4 tn4 = make_float4(0.f, 0.f, 0.f, 0.f);
    float  pnv = 0.f;
#pragma unroll
    for (int ks = 0; ks < KSPLIT; ks++) {
        float4 p4 = *(const float4*)&P[(size_t)ks * (BN_ROWS * T_TGT) + base];
        dot.x += p4.x; dot.y += p4.y; dot.z += p4.z; dot.w += p4.w;
        float4 t4 = *(const float4*)&tnp[ks * T_TGT + t0];
        tn4.x += t4.x; tn4.y += t4.y; tn4.z += t4.z; tn4.w += t4.w;
        pnv += pnp[ks * BN_ROWS + bn];
    }

    float res[4];
    const float d4[4] = {dot.x, dot.y, dot.z, dot.w};
    const float tt[4] = {tn4.x, tn4.y, tn4.z, tn4.w};
#pragma unroll
    for (int q = 0; q < 4; ++q) {
        const float den = pnv + tt[q];
        const float score = -((2.0f * d4[q] + 1e-4f) / (den + 1e-4f));
        const int id = ids[t0 + q];
        const float x = logits[bn * K_CLS + id];
        float pl;
        if (x >= 0.f) pl = 1.f / (1.f + expf(-x));
        else { float e = expf(x); pl = e / (1.f + e); }
        const float pos = 0.25f * (1.f - pl) * (1.f - pl) * (-logf(pl + 1e-8f));
        const float neg = 0.75f * pl * pl * (-logf(1.f - pl + 1e-8f));
        res[q] = score * 2.0f + (pos - neg);
    }
    *(float4*)&C[base] = make_float4(res[0], res[1], res[2], res[3]);
}

// ---------------- Jonker-Volgenant LSA, register-resident, one warp/image ----------------
__device__ __forceinline__ unsigned long long dkey(double d) {
    long long b = __double_as_longlong(d);
    return (unsigned long long)(b >= 0 ? (b ^ 0x8000000000000000LL) : ~b);
}
__device__ __forceinline__ double inv_dkey(unsigned long long k) {
    long long b = (k & 0x8000000000000000ULL) ? (long long)(k ^ 0x8000000000000000ULL)
                                              : ~(long long)k;
    return __longlong_as_double(b);
}

__global__ void __launch_bounds__(32) lsa_kernel(const float* __restrict__ C,
                                                 float* __restrict__ out_rows,
                                                 float* __restrict__ out_cols)
{
    const int b    = blockIdx.x;
    const int lane = threadIdx.x;
    const double INFD = 1e18;

    __shared__ double c[M_TGT][N_PRED];
    __shared__ double u[M_TGT + 1];
    __shared__ int    p[N_PRED + 1];
    __shared__ int    way[N_PRED + 1];

    for (int idx = lane; idx < M_TGT * N_PRED; idx += 32) {
        int t = idx / N_PRED, n = idx - t * N_PRED;
        c[t][n] = (double)C[(size_t)b * (N_PRED * T_TGT) + (size_t)n * T_TGT + b * M_TGT + t];
    }
    for (int j = lane; j <= N_PRED; j += 32) { p[j] = 0; way[j] = 0; }
    if (lane <= M_TGT) u[lane] = 0.0;

    const int jq0 = 1 + lane, jq1 = 33 + lane, jq2 = 65 + lane, jq3 = 97 + lane;
    const bool v3 = (jq3 <= N_PRED);
    double v_r0 = 0, v_r1 = 0, v_r2 = 0, v_r3 = 0;
    double m_r0, m_r1, m_r2, m_r3;
    bool  u_r0, u_r1, u_r2, u_r3;
    __syncwarp();

    for (int i = 1; i <= M_TGT; ++i) {
        if (lane == 0) p[0] = i;
        m_r0 = m_r1 = m_r2 = m_r3 = INFD;
        u_r0 = u_r1 = u_r2 = u_r3 = false;
        __syncwarp();

        int j0 = 0;
        while (true) {
            u_r0 |= (jq0 == j0); u_r1 |= (jq1 == j0);
            u_r2 |= (jq2 == j0); u_r3 |= (jq3 == j0);

            const int i0 = p[j0];
            const double ui0 = u[i0];
            const double* crow = c[i0 - 1];

            unsigned long long bestKey = 0xFFFFFFFFFFFFFFFFULL;
            int bestJ = 0x7FFFFFFF;
            if (!u_r0) {
                double cur = (crow[jq0 - 1] - ui0) - v_r0;
                if (cur < m_r0) { m_r0 = cur; way[jq0] = j0; }
                unsigned long long k = dkey(m_r0);
                if (k < bestKey) { bestKey = k; bestJ = jq0; }
            }
            if (!u_r1) {
                double cur = (crow[jq1 - 1] - ui0) - v_r1;
                if (cur < m_r1) { m_r1 = cur; way[jq1] = j0; }
                unsigned long long k = dkey(m_r1);
                if (k < bestKey) { bestKey = k; bestJ = jq1; }
            }
            if (!u_r2) {
                double cur = (crow[jq2 - 1] - ui0) - v_r2;
                if (cur < m_r2) { m_r2 = cur; way[jq2] = j0; }
                unsigned long long k = dkey(m_r2);
                if (k < bestKey) { bestKey = k; bestJ = jq2; }
            }
            if (v3 && !u_r3) {
                double cur = (crow[jq3 - 1] - ui0) - v_r3;
                if (cur < m_r3) { m_r3 = cur; way[jq3] = j0; }
                unsigned long long k = dkey(m_r3);
                if (k < bestKey) { bestKey = k; bestJ = jq3; }
            }

            const unsigned hi = (unsigned)(bestKey >> 32);
            const unsigned minHi = __reduce_min_sync(0xffffffff, hi);
            const unsigned lo = (hi == minHi) ? (unsigned)bestKey : 0xffffffffu;
            const unsigned minLo = __reduce_min_sync(0xffffffff, lo);
            const unsigned jc = (hi == minHi && (unsigned)bestKey == minLo)
                                ? (unsigned)bestJ : 0x7fffffffu;
            const int j1 = (int)__reduce_min_sync(0xffffffff, jc);
            const double delta = inv_dkey(((unsigned long long)minHi << 32) | minLo);

            if (u_r0) { u[p[jq0]] += delta; v_r0 -= delta; } else { m_r0 -= delta; }
            if (u_r1) { u[p[jq1]] += delta; v_r1 -= delta; } else { m_r1 -= delta; }
            if (u_r2) { u[p[jq2]] += delta; v_r2 -= delta; } else { m_r2 -= delta; }
            if (v3) { if (u_r3) { u[p[jq3]] += delta; v_r3 -= delta; } else { m_r3 -= delta; } }
            if (lane == 0) u[p[0]] += delta;

            __syncwarp();
            j0 = j1;
            if (p[j0] == 0) break;
        }

        if (lane == 0) {
            int jj = j0;
            while (jj != 0) { int jn = way[jj]; p[jj] = p[jn]; jj = jn; }
        }
        __syncwarp();
    }

    if (lane == 0) {
        int k = 0;
        for (int j = 1; j <= N_PRED; j++) {
            if (p[j] != 0) {
                out_rows[b * M_TGT + k] = (float)(j - 1);
                out_cols[b * M_TGT + k] = (float)(p[j] - 1);
                k++;
            }
        }
    }
}

// ---------------- launch ----------------
extern "C" void kernel_launch(void* const* d_in, const int* in_sizes, int n_in,
                              void* d_out, int out_size)
{
    const float* pred_masks   = (const float*)d_in[0];   // (8,100,160,160)
    const float* pred_logits  = (const float*)d_in[1];   // (8,100,80)
    const float* target_masks = (const float*)d_in[2];   // (160,160,160)
    const int*   tgt_ids      = (const int*)d_in[3];     // (160,)
    float* out = (float*)d_out;                          // [C | rows | cols]

    float* d_partial; cudaGetSymbolAddress((void**)&d_partial, g_partial);
    float* d_pnp;     cudaGetSymbolAddress((void**)&d_pnp, g_pnp);
    float* d_tnp;     cudaGetSymbolAddress((void**)&d_tnp, g_tnp);

    cudaFuncSetAttribute(gemm_mma_kernel,
                         cudaFuncAttributeMaxDynamicSharedMemorySize, SMEM_BYTES);

    dim3 ggrid(MBLKS, KSPLIT);
    gemm_mma_kernel<<<ggrid, 256, SMEM_BYTES>>>(pred_masks, target_masks,
                                                d_partial, d_pnp, d_tnp);

    finalize_kernel<<<(BN_ROWS * T_TGT / 4 + 255) / 256, 256>>>(d_partial, d_pnp, d_tnp,
                                                                pred_logits, tgt_ids, out);

    lsa_kernel<<<B_IMG, 32>>>(out,
                              out + BN_ROWS * T_TGT,
                              out + BN_ROWS * T_TGT + B_IMG * M_TGT);
}

// round 12
// speedup vs baseline: 1.2220x; 1.0104x over previous
#include <cuda_runtime.h>
#include <cstdint>

// ---------------- problem dimensions (fixed by the dataset) ----------------
#define B_IMG   8
#define N_PRED  100
#define T_TGT   160
#define M_TGT   20
#define K_CLS   80
#define HW      25600
#define BN_ROWS 800

// ---------------- mma.sync tf32 GEMM tiling ----------------
#define KSPLIT  20
#define KCHUNK  1280             // HW / KSPLIT
#define BK      16
#define NIT     (KCHUNK / BK)    // 80
#define MTILE   128
#define MBLKS   7                // ceil(800/128)
#define LDA_S   20               // smem row stride in floats (16 + 4 pad)
#define STAGE_F 5760             // floats per stage: 128*20 + 160*20
#define NSTAGE  8
#define SMEM_BYTES (NSTAGE * STAGE_F * 4)   // 184320

// ---------------- scratch (no allocations allowed) ----------------
__device__ float g_partial[KSPLIT * BN_ROWS * T_TGT];   // 10.24 MB, [ks][row][col]
__device__ float g_pnp[KSPLIT * BN_ROWS];
__device__ float g_tnp[KSPLIT * T_TGT];

// ---------------- helpers ----------------
__device__ __forceinline__ uint32_t smem_u32(const void* p) {
    uint32_t a;
    asm("{ .reg .u64 t; cvta.to.shared.u64 t, %1; cvt.u32.u64 %0, t; }" : "=r"(a) : "l"(p));
    return a;
}
__device__ __forceinline__ void cp16(uint32_t dst, const void* src, int sz) {
    asm volatile("cp.async.cg.shared.global [%0], [%1], 16, %2;"
                 :: "r"(dst), "l"(src), "r"(sz) : "memory");
}
__device__ __forceinline__ void cp_commit() {
    asm volatile("cp.async.commit_group;" ::: "memory");
}
__device__ __forceinline__ void mma_tf32(float* c, const uint32_t* a, const uint32_t* b) {
    asm volatile(
        "mma.sync.aligned.m16n8k8.row.col.f32.tf32.tf32.f32 "
        "{%0,%1,%2,%3}, {%4,%5,%6,%7}, {%8,%9}, {%0,%1,%2,%3};"
        : "+f"(c[0]), "+f"(c[1]), "+f"(c[2]), "+f"(c[3])
        : "r"(a[0]), "r"(a[1]), "r"(a[2]), "r"(a[3]), "r"(b[0]), "r"(b[1]));
}
// ldmatrix x4 on b16: four 8x8 b16 tiles == four 8x4 tf32 tiles; per-thread
// distribution (row=lane>>2, col=lane&3) matches the tf32 m16n8k8 fragment.
__device__ __forceinline__ void ldsm4(uint32_t* r, uint32_t addr) {
    asm volatile("ldmatrix.sync.aligned.m8n8.x4.shared.b16 {%0,%1,%2,%3}, [%4];"
                 : "=r"(r[0]), "=r"(r[1]), "=r"(r[2]), "=r"(r[3]) : "r"(addr));
}

// ---------------- tf32 mma.sync split-K GEMM + fused sumsq ----------------
// MTILE=128, 1 CTA/SM, grid (7,20)=140. 8-stage pipeline, 4 k-tiles / barrier,
// ldmatrix fragment loads.
__global__ void __launch_bounds__(256, 1)
gemm_mma_kernel(const float* __restrict__ A, const float* __restrict__ Bm,
                float* __restrict__ P, float* __restrict__ pnp, float* __restrict__ tnp)
{
    extern __shared__ __align__(16) float dsm[];

    const int tid   = threadIdx.x;
    const int wid   = tid >> 5;
    const int lane  = tid & 31;
    const int gid   = lane >> 2;     // 0..7
    const int tig   = lane & 3;      // 0..3
    const int warpM = wid >> 1;      // 0..3 -> 32 rows each
    const int warpN = wid & 1;       // 0..1 -> 80 cols each
    const int bx    = blockIdx.x;
    const int by    = blockIdx.y;
    const int mBase = bx * MTILE;
    const int kBase = by * KCHUNK;

    float acc[2][10][4];
#pragma unroll
    for (int tm = 0; tm < 2; tm++)
#pragma unroll
        for (int tn = 0; tn < 10; tn++)
#pragma unroll
            for (int i = 0; i < 4; i++) acc[tm][tn][i] = 0.f;

    const uint32_t sbase = smem_u32(dsm);

    // ldmatrix per-thread address offsets (bytes, within a stage)
    const int q = lane >> 3;
    const uint32_t offA = ((warpM * 32 + (q & 1) * 8 + (lane & 7)) * LDA_S
                           + (q >> 1) * 4) * 4;
    const uint32_t offB = (MTILE * LDA_S
                           + (warpN * 80 + (q >> 1) * 8 + (lane & 7)) * LDA_S
                           + (q & 1) * 4) * 4;

    auto issue = [&](int t) {
        const int buf = t & (NSTAGE - 1);
        const uint32_t sb = sbase + buf * (STAGE_F * 4);
        const int kOff = kBase + t * BK;
#pragma unroll
        for (int i = 0; i < 2; ++i) {
            const int f = tid * 2 + i;
            const int row = f >> 2, kq = f & 3;
            const int grow = mBase + row;
            const int ok = grow < BN_ROWS;
            const float* src = A + (size_t)(ok ? grow : 0) * HW + kOff + kq * 4;
            cp16(sb + row * (LDA_S * 4) + kq * 16, src, ok ? 16 : 0);
        }
#pragma unroll
        for (int i = 0; i < 3; ++i) {
            const int f = tid + i * 256;
            if (f < T_TGT * 4) {
                const int row = f >> 2, kq = f & 3;
                cp16(sb + (MTILE * LDA_S * 4) + row * (LDA_S * 4) + kq * 16,
                     Bm + (size_t)row * HW + kOff + kq * 4, 16);
            }
        }
        cp_commit();
    };

    // fused sumsq bookkeeping
    const int sq_arow = tid >> 1;              // 0..127
    const int sq_akh  = (tid & 1) * 8;         // 0 or 8
    const int sq_m    = tid >> 4;              // 0..15
    const int sq_k    = tid & 15;
    const int sq_br0  = bx + 7 * sq_m;               // < 160 always
    const int sq_br1  = bx + 7 * (sq_m + 16);        // may be >= 160
    const bool sq_b1ok = (sq_br1 < T_TGT);
    float accA = 0.f, accB0 = 0.f, accB1 = 0.f;

    auto compute = [&](int t) {
        const int buf = t & (NSTAGE - 1);
        const uint32_t sb = sbase + buf * (STAGE_F * 4);
        const float* asf = dsm + buf * STAGE_F;
        const float* bsf = asf + MTILE * LDA_S;

        // fused sumsq from smem
        {
            const float2* a2 = (const float2*)(asf + sq_arow * LDA_S + sq_akh);
#pragma unroll
            for (int i = 0; i < 4; ++i) {
                float2 v = a2[i];
                accA += v.x * v.x + v.y * v.y;
            }
            float b0 = bsf[sq_br0 * LDA_S + sq_k];
            accB0 += b0 * b0;
            if (sq_b1ok) {
                float b1 = bsf[sq_br1 * LDA_S + sq_k];
                accB1 += b1 * b1;
            }
        }

#pragma unroll
        for (int s = 0; s < 2; ++s) {
            uint32_t af[2][4], bf[5][4];
            ldsm4(af[0], sb + offA + s * 32);
            ldsm4(af[1], sb + offA + (16 * LDA_S * 4) + s * 32);
#pragma unroll
            for (int tp = 0; tp < 5; tp++)
                ldsm4(bf[tp], sb + offB + tp * (16 * LDA_S * 4) + s * 32);
#pragma unroll
            for (int tm = 0; tm < 2; tm++)
#pragma unroll
                for (int tp = 0; tp < 5; tp++) {
                    mma_tf32(acc[tm][2 * tp],     af[tm], &bf[tp][0]);
                    mma_tf32(acc[tm][2 * tp + 1], af[tm], &bf[tp][2]);
                }
        }
    };

    // prologue: 4 stages in flight (stages 0..3)
    issue(0); issue(1); issue(2); issue(3);

    for (int t = 0; t < NIT; t += 4) {
        // tiles t..t+3 are the only outstanding groups -> drain them all
        asm volatile("cp.async.wait_group 0;" ::: "memory");
        __syncthreads();
        // refill the 4 stages consumed LAST iteration (disjoint from t..t+3)
        if (t + 4 < NIT) { issue(t + 4); issue(t + 5); issue(t + 6); issue(t + 7); }

        compute(t);
        compute(t + 1);
        compute(t + 2);
        compute(t + 3);
    }
    __syncthreads();   // protect smem reuse below

    // ---- sumsq reduction (smem reuse after mainloop) ----
    dsm[tid] = accA;
    dsm[256 + tid] = accB0;
    dsm[512 + tid] = sq_b1ok ? accB1 : 0.f;
    __syncthreads();
    if (tid < 128) {
        const float s = dsm[2 * tid] + dsm[2 * tid + 1];
        const int gr = mBase + tid;
        if (gr < BN_ROWS) pnp[by * BN_ROWS + gr] = s;
    } else if (tid < 160) {
        const int m = tid - 128;
        const int r = bx + 7 * m;
        if (r < T_TGT) {
            const int base = (m < 16) ? (256 + m * 16) : (512 + (m - 16) * 16);
            float s = 0.f;
#pragma unroll
            for (int k = 0; k < 16; ++k) s += dsm[base + k];
            tnp[by * T_TGT + r] = s;
        }
    }

    // ---- epilogue: write P[ks][row][col] ----
    float* dst = P + (size_t)by * (BN_ROWS * T_TGT);
#pragma unroll
    for (int tm = 0; tm < 2; tm++) {
        const int r0 = mBase + warpM * 32 + tm * 16 + gid;
        const int r1 = r0 + 8;
#pragma unroll
        for (int tn = 0; tn < 10; tn++) {
            const int col = warpN * 80 + tn * 8 + tig * 2;
            if (r0 < BN_ROWS)
                *(float2*)&dst[(size_t)r0 * T_TGT + col] = make_float2(acc[tm][tn][0], acc[tm][tn][1]);
            if (r1 < BN_ROWS)
                *(float2*)&dst[(size_t)r1 * T_TGT + col] = make_float2(acc[tm][tn][2], acc[tm][tn][3]);
        }
    }
}

// ---------------- finalize: ksplit-sum + norms + dice + focal -> C ----------------
__global__ void __launch_bounds__(256) finalize_kernel(const float* __restrict__ P,
                                                       const float* __restrict__ pnp,
                                                       const float* __restrict__ tnp,
                                                       const float* __restrict__ logits,
                                                       const int*   __restrict__ ids,
                                                       float* __restrict__ C)
{
    const int base = (blockIdx.x * 256 + threadIdx.x) * 4;
    if (base >= BN_ROWS * T_TGT) return;
    const int bn = base / T_TGT;
    const int t0 = base - bn * T_TGT;

    float4 dot = make_float4(0.f, 0.f, 0.f, 0.f);
    float4 tn4 = make_float4(0.f, 0.f, 0.f, 0.f);
    float  pnv = 0.f;
#pragma unroll
    for (int ks = 0; ks < KSPLIT; ks++) {
        float4 p4 = *(const float4*)&P[(size_t)ks * (BN_ROWS * T_TGT) + base];
        dot.x += p4.x; dot.y += p4.y; dot.z += p4.z; dot.w += p4.w;
        float4 t4 = *(const float4*)&tnp[ks * T_TGT + t0];
        tn4.x += t4.x; tn4.y += t4.y; tn4.z += t4.z; tn4.w += t4.w;
        pnv += pnp[ks * BN_ROWS + bn];
    }

    float res[4];
    const float d4[4] = {dot.x, dot.y, dot.z, dot.w};
    const float tt[4] = {tn4.x, tn4.y, tn4.z, tn4.w};
#pragma unroll
    for (int q = 0; q < 4; ++q) {
        const float den = pnv + tt[q];
        const float score = -((2.0f * d4[q] + 1e-4f) / (den + 1e-4f));
        const int id = ids[t0 + q];
        const float x = logits[bn * K_CLS + id];
        float pl;
        if (x >= 0.f) pl = 1.f / (1.f + expf(-x));
        else { float e = expf(x); pl = e / (1.f + e); }
        const float pos = 0.25f * (1.f - pl) * (1.f - pl) * (-logf(pl + 1e-8f));
        const float neg = 0.75f * pl * pl * (-logf(1.f - pl + 1e-8f));
        res[q] = score * 2.0f + (pos - neg);
    }
    *(float4*)&C[base] = make_float4(res[0], res[1], res[2], res[3]);
}

// ---------------- Jonker-Volgenant LSA, register-resident, one warp/image ----------------
__device__ __forceinline__ unsigned long long dkey(double d) {
    long long b = __double_as_longlong(d);
    return (unsigned long long)(b >= 0 ? (b ^ 0x8000000000000000LL) : ~b);
}
__device__ __forceinline__ double inv_dkey(unsigned long long k) {
    long long b = (k & 0x8000000000000000ULL) ? (long long)(k ^ 0x8000000000000000ULL)
                                              : ~(long long)k;
    return __longlong_as_double(b);
}

__global__ void __launch_bounds__(32) lsa_kernel(const float* __restrict__ C,
                                                 float* __restrict__ out_rows,
                                                 float* __restrict__ out_cols)
{
    const int b    = blockIdx.x;
    const int lane = threadIdx.x;
    const double INFD = 1e18;

    __shared__ double c[M_TGT][N_PRED];
    __shared__ double u[M_TGT + 1];
    __shared__ int    p[N_PRED + 1];
    __shared__ int    way[N_PRED + 1];

    for (int idx = lane; idx < M_TGT * N_PRED; idx += 32) {
        int t = idx / N_PRED, n = idx - t * N_PRED;
        c[t][n] = (double)C[(size_t)b * (N_PRED * T_TGT) + (size_t)n * T_TGT + b * M_TGT + t];
    }
    for (int j = lane; j <= N_PRED; j += 32) { p[j] = 0; way[j] = 0; }
    if (lane <= M_TGT) u[lane] = 0.0;

    const int jq0 = 1 + lane, jq1 = 33 + lane, jq2 = 65 + lane, jq3 = 97 + lane;
    const bool v3 = (jq3 <= N_PRED);
    double v_r0 = 0, v_r1 = 0, v_r2 = 0, v_r3 = 0;
    double m_r0, m_r1, m_r2, m_r3;
    bool  u_r0, u_r1, u_r2, u_r3;
    __syncwarp();

    for (int i = 1; i <= M_TGT; ++i) {
        if (lane == 0) p[0] = i;
        m_r0 = m_r1 = m_r2 = m_r3 = INFD;
        u_r0 = u_r1 = u_r2 = u_r3 = false;
        __syncwarp();

        int j0 = 0;
        while (true) {
            u_r0 |= (jq0 == j0); u_r1 |= (jq1 == j0);
            u_r2 |= (jq2 == j0); u_r3 |= (jq3 == j0);

            const int i0 = p[j0];
            const double ui0 = u[i0];
            const double* crow = c[i0 - 1];

            unsigned long long bestKey = 0xFFFFFFFFFFFFFFFFULL;
            int bestJ = 0x7FFFFFFF;
            if (!u_r0) {
                double cur = (crow[jq0 - 1] - ui0) - v_r0;
                if (cur < m_r0) { m_r0 = cur; way[jq0] = j0; }
                unsigned long long k = dkey(m_r0);
                if (k < bestKey) { bestKey = k; bestJ = jq0; }
            }
            if (!u_r1) {
                double cur = (crow[jq1 - 1] - ui0) - v_r1;
                if (cur < m_r1) { m_r1 = cur; way[jq1] = j0; }
                unsigned long long k = dkey(m_r1);
                if (k < bestKey) { bestKey = k; bestJ = jq1; }
            }
            if (!u_r2) {
                double cur = (crow[jq2 - 1] - ui0) - v_r2;
                if (cur < m_r2) { m_r2 = cur; way[jq2] = j0; }
                unsigned long long k = dkey(m_r2);
                if (k < bestKey) { bestKey = k; bestJ = jq2; }
            }
            if (v3 && !u_r3) {
                double cur = (crow[jq3 - 1] - ui0) - v_r3;
                if (cur < m_r3) { m_r3 = cur; way[jq3] = j0; }
                unsigned long long k = dkey(m_r3);
                if (k < bestKey) { bestKey = k; bestJ = jq3; }
            }

            const unsigned hi = (unsigned)(bestKey >> 32);
            const unsigned minHi = __reduce_min_sync(0xffffffff, hi);
            const unsigned lo = (hi == minHi) ? (unsigned)bestKey : 0xffffffffu;
            const unsigned minLo = __reduce_min_sync(0xffffffff, lo);
            const unsigned jc = (hi == minHi && (unsigned)bestKey == minLo)
                                ? (unsigned)bestJ : 0x7fffffffu;
            const int j1 = (int)__reduce_min_sync(0xffffffff, jc);
            const double delta = inv_dkey(((unsigned long long)minHi << 32) | minLo);

            if (u_r0) { u[p[jq0]] += delta; v_r0 -= delta; } else { m_r0 -= delta; }
            if (u_r1) { u[p[jq1]] += delta; v_r1 -= delta; } else { m_r1 -= delta; }
            if (u_r2) { u[p[jq2]] += delta; v_r2 -= delta; } else { m_r2 -= delta; }
            if (v3) { if (u_r3) { u[p[jq3]] += delta; v_r3 -= delta; } else { m_r3 -= delta; } }
            if (lane == 0) u[p[0]] += delta;

            __syncwarp();
            j0 = j1;
            if (p[j0] == 0) break;
        }

        if (lane == 0) {
            int jj = j0;
            while (jj != 0) { int jn = way[jj]; p[jj] = p[jn]; jj = jn; }
        }
        __syncwarp();
    }

    if (lane == 0) {
        int k = 0;
        for (int j = 1; j <= N_PRED; j++) {
            if (p[j] != 0) {
                out_rows[b * M_TGT + k] = (float)(j - 1);
                out_cols[b * M_TGT + k] = (float)(p[j] - 1);
                k++;
            }
        }
    }
}

// ---------------- launch ----------------
extern "C" void kernel_launch(void* const* d_in, const int* in_sizes, int n_in,
                              void* d_out, int out_size)
{
    const float* pred_masks   = (const float*)d_in[0];   // (8,100,160,160)
    const float* pred_logits  = (const float*)d_in[1];   // (8,100,80)
    const float* target_masks = (const float*)d_in[2];   // (160,160,160)
    const int*   tgt_ids      = (const int*)d_in[3];     // (160,)
    float* out = (float*)d_out;                          // [C | rows | cols]

    float* d_partial; cudaGetSymbolAddress((void**)&d_partial, g_partial);
    float* d_pnp;     cudaGetSymbolAddress((void**)&d_pnp, g_pnp);
    float* d_tnp;     cudaGetSymbolAddress((void**)&d_tnp, g_tnp);

    cudaFuncSetAttribute(gemm_mma_kernel,
                         cudaFuncAttributeMaxDynamicSharedMemorySize, SMEM_BYTES);

    dim3 ggrid(MBLKS, KSPLIT);
    gemm_mma_kernel<<<ggrid, 256, SMEM_BYTES>>>(pred_masks, target_masks,
                                                d_partial, d_pnp, d_tnp);

    finalize_kernel<<<(BN_ROWS * T_TGT / 4 + 255) / 256, 256>>>(d_partial, d_pnp, d_tnp,
                                                                pred_logits, tgt_ids, out);

    lsa_kernel<<<B_IMG, 32>>>(out,
                              out + BN_ROWS * T_TGT,
                              out + BN_ROWS * T_TGT + B_IMG * M_TGT);
}

// round 13
// speedup vs baseline: 1.2290x; 1.0057x over previous
#include <cuda_runtime.h>
#include <cstdint>

// ---------------- problem dimensions (fixed by the dataset) ----------------
#define B_IMG   8
#define N_PRED  100
#define T_TGT   160
#define M_TGT   20
#define K_CLS   80
#define HW      25600
#define BN_ROWS 800

// ---------------- mma.sync tf32 GEMM tiling ----------------
#define KSPLIT  20
#define KCHUNK  1280             // HW / KSPLIT
#define BK      16
#define NIT     (KCHUNK / BK)    // 80
#define MTILE   128
#define MBLKS   7                // ceil(800/128)
#define LDA_S   20               // smem row stride in floats (16 + 4 pad)
#define STAGE_F 5760             // floats per stage: 128*20 + 160*20
#define NSTAGE  8
#define SMEM_BYTES (NSTAGE * STAGE_F * 4)   // 184320

// ---------------- scratch (no allocations allowed) ----------------
__device__ float g_partial[KSPLIT * BN_ROWS * T_TGT];   // 10.24 MB, [ks][row][col]
__device__ float g_pnp[KSPLIT * BN_ROWS];
__device__ float g_tnp[KSPLIT * T_TGT];

// ---------------- helpers ----------------
__device__ __forceinline__ uint32_t smem_u32(const void* p) {
    uint32_t a;
    asm("{ .reg .u64 t; cvta.to.shared.u64 t, %1; cvt.u32.u64 %0, t; }" : "=r"(a) : "l"(p));
    return a;
}
__device__ __forceinline__ void cp16(uint32_t dst, const void* src, int sz) {
    asm volatile("cp.async.cg.shared.global [%0], [%1], 16, %2;"
                 :: "r"(dst), "l"(src), "r"(sz) : "memory");
}
__device__ __forceinline__ void cp_commit() {
    asm volatile("cp.async.commit_group;" ::: "memory");
}
__device__ __forceinline__ void mma_tf32(float* c, const uint32_t* a, const uint32_t* b) {
    asm volatile(
        "mma.sync.aligned.m16n8k8.row.col.f32.tf32.tf32.f32 "
        "{%0,%1,%2,%3}, {%4,%5,%6,%7}, {%8,%9}, {%0,%1,%2,%3};"
        : "+f"(c[0]), "+f"(c[1]), "+f"(c[2]), "+f"(c[3])
        : "r"(a[0]), "r"(a[1]), "r"(a[2]), "r"(a[3]), "r"(b[0]), "r"(b[1]));
}
// ldmatrix x4 on b16: four 8x8 b16 tiles == four 8x4 tf32 tiles; per-thread
// distribution (row=lane>>2, col=lane&3) matches the tf32 m16n8k8 fragment.
__device__ __forceinline__ void ldsm4(uint32_t* r, uint32_t addr) {
    asm volatile("ldmatrix.sync.aligned.m8n8.x4.shared.b16 {%0,%1,%2,%3}, [%4];"
                 : "=r"(r[0]), "=r"(r[1]), "=r"(r[2]), "=r"(r[3]) : "r"(addr));
}

// ---------------- tf32 mma.sync split-K GEMM + fused sumsq ----------------
// MTILE=128, 1 CTA/SM, grid (7,20)=140. 8-stage pipeline, 4 k-tiles / barrier,
// ldmatrix fragment loads.
__global__ void __launch_bounds__(256, 1)
gemm_mma_kernel(const float* __restrict__ A, const float* __restrict__ Bm,
                float* __restrict__ P, float* __restrict__ pnp, float* __restrict__ tnp)
{
    extern __shared__ __align__(16) float dsm[];

    const int tid   = threadIdx.x;
    const int wid   = tid >> 5;
    const int lane  = tid & 31;
    const int gid   = lane >> 2;     // 0..7
    const int tig   = lane & 3;      // 0..3
    const int warpM = wid >> 1;      // 0..3 -> 32 rows each
    const int warpN = wid & 1;       // 0..1 -> 80 cols each
    const int bx    = blockIdx.x;
    const int by    = blockIdx.y;
    const int mBase = bx * MTILE;
    const int kBase = by * KCHUNK;

    float acc[2][10][4];
#pragma unroll
    for (int tm = 0; tm < 2; tm++)
#pragma unroll
        for (int tn = 0; tn < 10; tn++)
#pragma unroll
            for (int i = 0; i < 4; i++) acc[tm][tn][i] = 0.f;

    const uint32_t sbase = smem_u32(dsm);

    // ldmatrix per-thread address offsets (bytes, within a stage)
    const int q = lane >> 3;
    const uint32_t offA = ((warpM * 32 + (q & 1) * 8 + (lane & 7)) * LDA_S
                           + (q >> 1) * 4) * 4;
    const uint32_t offB = (MTILE * LDA_S
                           + (warpN * 80 + (q >> 1) * 8 + (lane & 7)) * LDA_S
                           + (q & 1) * 4) * 4;

    auto issue = [&](int t) {
        const int buf = t & (NSTAGE - 1);
        const uint32_t sb = sbase + buf * (STAGE_F * 4);
        const int kOff = kBase + t * BK;
#pragma unroll
        for (int i = 0; i < 2; ++i) {
            const int f = tid * 2 + i;
            const int row = f >> 2, kq = f & 3;
            const int grow = mBase + row;
            const int ok = grow < BN_ROWS;
            const float* src = A + (size_t)(ok ? grow : 0) * HW + kOff + kq * 4;
            cp16(sb + row * (LDA_S * 4) + kq * 16, src, ok ? 16 : 0);
        }
#pragma unroll
        for (int i = 0; i < 3; ++i) {
            const int f = tid + i * 256;
            if (f < T_TGT * 4) {
                const int row = f >> 2, kq = f & 3;
                cp16(sb + (MTILE * LDA_S * 4) + row * (LDA_S * 4) + kq * 16,
                     Bm + (size_t)row * HW + kOff + kq * 4, 16);
            }
        }
        cp_commit();
    };

    // fused sumsq bookkeeping
    const int sq_arow = tid >> 1;              // 0..127
    const int sq_akh  = (tid & 1) * 8;         // 0 or 8
    const int sq_m    = tid >> 4;              // 0..15
    const int sq_k    = tid & 15;
    const int sq_br0  = bx + 7 * sq_m;               // < 160 always
    const int sq_br1  = bx + 7 * (sq_m + 16);        // may be >= 160
    const bool sq_b1ok = (sq_br1 < T_TGT);
    float accA = 0.f, accB0 = 0.f, accB1 = 0.f;

    auto compute = [&](int t) {
        const int buf = t & (NSTAGE - 1);
        const uint32_t sb = sbase + buf * (STAGE_F * 4);
        const float* asf = dsm + buf * STAGE_F;
        const float* bsf = asf + MTILE * LDA_S;

        // fused sumsq from smem
        {
            const float2* a2 = (const float2*)(asf + sq_arow * LDA_S + sq_akh);
#pragma unroll
            for (int i = 0; i < 4; ++i) {
                float2 v = a2[i];
                accA += v.x * v.x + v.y * v.y;
            }
            float b0 = bsf[sq_br0 * LDA_S + sq_k];
            accB0 += b0 * b0;
            if (sq_b1ok) {
                float b1 = bsf[sq_br1 * LDA_S + sq_k];
                accB1 += b1 * b1;
            }
        }

#pragma unroll
        for (int s = 0; s < 2; ++s) {
            uint32_t af[2][4], bf[5][4];
            ldsm4(af[0], sb + offA + s * 32);
            ldsm4(af[1], sb + offA + (16 * LDA_S * 4) + s * 32);
#pragma unroll
            for (int tp = 0; tp < 5; tp++)
                ldsm4(bf[tp], sb + offB + tp * (16 * LDA_S * 4) + s * 32);
#pragma unroll
            for (int tm = 0; tm < 2; tm++)
#pragma unroll
                for (int tp = 0; tp < 5; tp++) {
                    mma_tf32(acc[tm][2 * tp],     af[tm], &bf[tp][0]);
                    mma_tf32(acc[tm][2 * tp + 1], af[tm], &bf[tp][2]);
                }
        }
    };

    // prologue: 4 stages in flight (stages 0..3)
    issue(0); issue(1); issue(2); issue(3);

    for (int t = 0; t < NIT; t += 4) {
        // tiles t..t+3 are the only outstanding groups -> drain them all
        asm volatile("cp.async.wait_group 0;" ::: "memory");
        __syncthreads();
        // refill the 4 stages consumed LAST iteration (disjoint from t..t+3)
        if (t + 4 < NIT) { issue(t + 4); issue(t + 5); issue(t + 6); issue(t + 7); }

        compute(t);
        compute(t + 1);
        compute(t + 2);
        compute(t + 3);
    }
    __syncthreads();   // protect smem reuse below

    // ---- sumsq reduction (smem reuse after mainloop) ----
    dsm[tid] = accA;
    dsm[256 + tid] = accB0;
    dsm[512 + tid] = sq_b1ok ? accB1 : 0.f;
    __syncthreads();
    if (tid < 128) {
        const float s = dsm[2 * tid] + dsm[2 * tid + 1];
        const int gr = mBase + tid;
        if (gr < BN_ROWS) pnp[by * BN_ROWS + gr] = s;
    } else if (tid < 160) {
        const int m = tid - 128;
        const int r = bx + 7 * m;
        if (r < T_TGT) {
            const int base = (m < 16) ? (256 + m * 16) : (512 + (m - 16) * 16);
            float s = 0.f;
#pragma unroll
            for (int k = 0; k < 16; ++k) s += dsm[base + k];
            tnp[by * T_TGT + r] = s;
        }
    }

    // ---- epilogue: write P[ks][row][col] ----
    float* dst = P + (size_t)by * (BN_ROWS * T_TGT);
#pragma unroll
    for (int tm = 0; tm < 2; tm++) {
        const int r0 = mBase + warpM * 32 + tm * 16 + gid;
        const int r1 = r0 + 8;
#pragma unroll
        for (int tn = 0; tn < 10; tn++) {
            const int col = warpN * 80 + tn * 8 + tig * 2;
            if (r0 < BN_ROWS)
                *(float2*)&dst[(size_t)r0 * T_TGT + col] = make_float2(acc[tm][tn][0], acc[tm][tn][1]);
            if (r1 < BN_ROWS)
                *(float2*)&dst[(size_t)r1 * T_TGT + col] = make_float2(acc[tm][tn][2], acc[tm][tn][3]);
        }
    }
}

// ---------------- finalize: ksplit-sum + norms + dice + focal -> C ----------------
__global__ void __launch_bounds__(256) finalize_kernel(const float* __restrict__ P,
                                                       const float* __restrict__ pnp,
                                                       const float* __restrict__ tnp,
                                                       const float* __restrict__ logits,
                                                       const int*   __restrict__ ids,
                                                       float* __restrict__ C)
{
    const int base = (blockIdx.x * 256 + threadIdx.x) * 4;
    if (base >= BN_ROWS * T_TGT) return;
    const int bn = base / T_TGT;
    const int t0 = base - bn * T_TGT;

    float4 dot = make_float4(0.f, 0.f, 0.f, 0.f);
    float4 tn4 = make_float4(0.f, 0.f, 0.f, 0.f);
    float  pnv = 0.f;
#pragma unroll
    for (int ks = 0; ks < KSPLIT; ks++) {
        float4 p4 = *(const float4*)&P[(size_t)ks * (BN_ROWS * T_TGT) + base];
        dot.x += p4.x; dot.y += p4.y; dot.z += p4.z; dot.w += p4.w;
        float4 t4 = *(const float4*)&tnp[ks * T_TGT + t0];
        tn4.x += t4.x; tn4.y += t4.y; tn4.z += t4.z; tn4.w += t4.w;
        pnv += pnp[ks * BN_ROWS + bn];
    }

    float res[4];
    const float d4[4] = {dot.x, dot.y, dot.z, dot.w};
    const float tt[4] = {tn4.x, tn4.y, tn4.z, tn4.w};
#pragma unroll
    for (int q = 0; q < 4; ++q) {
        const float den = pnv + tt[q];
        const float score = -((2.0f * d4[q] + 1e-4f) / (den + 1e-4f));
        const int id = ids[t0 + q];
        const float x = logits[bn * K_CLS + id];
        float pl;
        if (x >= 0.f) pl = 1.f / (1.f + expf(-x));
        else { float e = expf(x); pl = e / (1.f + e); }
        const float pos = 0.25f * (1.f - pl) * (1.f - pl) * (-logf(pl + 1e-8f));
        const float neg = 0.75f * pl * pl * (-logf(1.f - pl + 1e-8f));
        res[q] = score * 2.0f + (pos - neg);
    }
    *(float4*)&C[base] = make_float4(res[0], res[1], res[2], res[3]);
}

// ---------------- Jonker-Volgenant LSA, register-resident, one warp/image ----------------
__device__ __forceinline__ unsigned long long dkey(double d) {
    long long b = __double_as_longlong(d);
    return (unsigned long long)(b >= 0 ? (b ^ 0x8000000000000000LL) : ~b);
}
__device__ __forceinline__ double inv_dkey(unsigned long long k) {
    long long b = (k & 0x8000000000000000ULL) ? (long long)(k ^ 0x8000000000000000ULL)
                                              : ~(long long)k;
    return __longlong_as_double(b);
}

__global__ void __launch_bounds__(32) lsa_kernel(const float* __restrict__ C,
                                                 float* __restrict__ out_rows,
                                                 float* __restrict__ out_cols)
{
    const int b    = blockIdx.x;
    const int lane = threadIdx.x;
    const double INFD = 1e18;

    __shared__ double c[M_TGT][N_PRED];
    __shared__ double u[M_TGT + 1];
    __shared__ int    p[N_PRED + 1];
    __shared__ int    way[N_PRED + 1];

    for (int idx = lane; idx < M_TGT * N_PRED; idx += 32) {
        int t = idx / N_PRED, n = idx - t * N_PRED;
        c[t][n] = (double)C[(size_t)b * (N_PRED * T_TGT) + (size_t)n * T_TGT + b * M_TGT + t];
    }
    for (int j = lane; j <= N_PRED; j += 32) { p[j] = 0; way[j] = 0; }
    if (lane <= M_TGT) u[lane] = 0.0;

    const int jq0 = 1 + lane, jq1 = 33 + lane, jq2 = 65 + lane, jq3 = 97 + lane;
    const bool v3 = (jq3 <= N_PRED);
    double v_r0 = 0, v_r1 = 0, v_r2 = 0, v_r3 = 0;
    double m_r0, m_r1, m_r2, m_r3;
    bool  u_r0, u_r1, u_r2, u_r3;
    __syncwarp();

    for (int i = 1; i <= M_TGT; ++i) {
        if (lane == 0) p[0] = i;
        m_r0 = m_r1 = m_r2 = m_r3 = INFD;
        u_r0 = u_r1 = u_r2 = u_r3 = false;
        __syncwarp();

        int j0 = 0;
        while (true) {
            u_r0 |= (jq0 == j0); u_r1 |= (jq1 == j0);
            u_r2 |= (jq2 == j0); u_r3 |= (jq3 == j0);

            const int i0 = p[j0];
            const double ui0 = u[i0];
            const double* crow = c[i0 - 1];

            unsigned long long bestKey = 0xFFFFFFFFFFFFFFFFULL;
            int bestJ = 0x7FFFFFFF;
            if (!u_r0) {
                double cur = (crow[jq0 - 1] - ui0) - v_r0;
                if (cur < m_r0) { m_r0 = cur; way[jq0] = j0; }
                unsigned long long k = dkey(m_r0);
                if (k < bestKey) { bestKey = k; bestJ = jq0; }
            }
            if (!u_r1) {
                double cur = (crow[jq1 - 1] - ui0) - v_r1;
                if (cur < m_r1) { m_r1 = cur; way[jq1] = j0; }
                unsigned long long k = dkey(m_r1);
                if (k < bestKey) { bestKey = k; bestJ = jq1; }
            }
            if (!u_r2) {
                double cur = (crow[jq2 - 1] - ui0) - v_r2;
                if (cur < m_r2) { m_r2 = cur; way[jq2] = j0; }
                unsigned long long k = dkey(m_r2);
                if (k < bestKey) { bestKey = k; bestJ = jq2; }
            }
            if (v3 && !u_r3) {
                double cur = (crow[jq3 - 1] - ui0) - v_r3;
                if (cur < m_r3) { m_r3 = cur; way[jq3] = j0; }
                unsigned long long k = dkey(m_r3);
                if (k < bestKey) { bestKey = k; bestJ = jq3; }
            }

            const unsigned hi = (unsigned)(bestKey >> 32);
            const unsigned minHi = __reduce_min_sync(0xffffffff, hi);
            const unsigned lo = (hi == minHi) ? (unsigned)bestKey : 0xffffffffu;
            const unsigned minLo = __reduce_min_sync(0xffffffff, lo);
            const unsigned jc = (hi == minHi && (unsigned)bestKey == minLo)
                                ? (unsigned)bestJ : 0x7fffffffu;
            const int j1 = (int)__reduce_min_sync(0xffffffff, jc);
            const double delta = inv_dkey(((unsigned long long)minHi << 32) | minLo);

            if (u_r0) { u[p[jq0]] += delta; v_r0 -= delta; } else { m_r0 -= delta; }
            if (u_r1) { u[p[jq1]] += delta; v_r1 -= delta; } else { m_r1 -= delta; }
            if (u_r2) { u[p[jq2]] += delta; v_r2 -= delta; } else { m_r2 -= delta; }
            if (v3) { if (u_r3) { u[p[jq3]] += delta; v_r3 -= delta; } else { m_r3 -= delta; } }
            if (lane == 0) u[p[0]] += delta;

            __syncwarp();
            j0 = j1;
            if (p[j0] == 0) break;
        }

        if (lane == 0) {
            int jj = j0;
            while (jj != 0) { int jn = way[jj]; p[jj] = p[jn]; jj = jn; }
        }
        __syncwarp();
    }

    if (lane == 0) {
        int k = 0;
        for (int j = 1; j <= N_PRED; j++) {
            if (p[j] != 0) {
                out_rows[b * M_TGT + k] = (float)(j - 1);
                out_cols[b * M_TGT + k] = (float)(p[j] - 1);
                k++;
            }
        }
    }
}

// ---------------- launch ----------------
extern "C" void kernel_launch(void* const* d_in, const int* in_sizes, int n_in,
                              void* d_out, int out_size)
{
    const float* pred_masks   = (const float*)d_in[0];   // (8,100,160,160)
    const float* pred_logits  = (const float*)d_in[1];   // (8,100,80)
    const float* target_masks = (const float*)d_in[2];   // (160,160,160)
    const int*   tgt_ids      = (const int*)d_in[3];     // (160,)
    float* out = (float*)d_out;                          // [C | rows | cols]

    float* d_partial; cudaGetSymbolAddress((void**)&d_partial, g_partial);
    float* d_pnp;     cudaGetSymbolAddress((void**)&d_pnp, g_pnp);
    float* d_tnp;     cudaGetSymbolAddress((void**)&d_tnp, g_tnp);

    cudaFuncSetAttribute(gemm_mma_kernel,
                         cudaFuncAttributeMaxDynamicSharedMemorySize, SMEM_BYTES);

    dim3 ggrid(MBLKS, KSPLIT);
    gemm_mma_kernel<<<ggrid, 256, SMEM_BYTES>>>(pred_masks, target_masks,
                                                d_partial, d_pnp, d_tnp);

    finalize_kernel<<<(BN_ROWS * T_TGT / 4 + 255) / 256, 256>>>(d_partial, d_pnp, d_tnp,
                                                                pred_logits, tgt_ids, out);

    lsa_kernel<<<B_IMG, 32>>>(out,
                              out + BN_ROWS * T_TGT,
                              out + BN_ROWS * T_TGT + B_IMG * M_TGT);
}